// round 15
// baseline (speedup 1.0000x reference)
#include <cuda_runtime.h>
#include <cuda_bf16.h>
#include <cuda_fp16.h>
#include <math.h>
#include <stdint.h>

#define NB   32
#define DIM  256
#define DI   128
#define HW   4096
#define CNT  (NB*HW)
#define W2SCALE 256.0f   // scale W2 & bias_p; BN normalization cancels it exactly

// ---------------------------------------------------------------------------
// Device scratch
// ---------------------------------------------------------------------------
__device__ float    d_xsum[NB*DIM];
__device__ float    d_tp[NB*DI*DI];
__device__ float    d_biasp[NB*DIM];
__device__ __half   d_wouth[DIM*DI];                 // w_out fp16 [256][128]
__device__ __half   d_W2h[(size_t)NB*DIM*DIM];
// x in fp16, k-pair packed: [n][hwt(32)][kp(128)][hw(128)] u32
__device__ uint32_t d_xh[(size_t)NB*32*128*128];     // 67 MB
__device__ __half   d_ph[(size_t)NB*DIM*HW];         // pre-BN p (scaled x256), 67 MB
__device__ float    d_chsum[DIM];
__device__ float    d_chsumsq[DIM];

__device__ __forceinline__ uint32_t smem_u32(const void* p) {
    uint32_t a;
    asm("{ .reg .u64 t; cvta.to.shared.u64 t, %1; cvt.u32.u64 %0, t; }" : "=r"(a) : "l"(p));
    return a;
}

// ---------------------------------------------------------------------------
// K0: convert x -> packed fp16 blob + per-(n,c) channel sums.
// Blocks (kp<16, n==0) also convert w_out fp32->fp16. Block (0,0) zeroes stats.
// ---------------------------------------------------------------------------
__global__ void cvtxsum_kernel(const float* __restrict__ x,
                               const float* __restrict__ w_out) {
    const int kp = blockIdx.x, n = blockIdx.y, tid = threadIdx.x;
    if (n == 0 && kp == 0) {
        d_chsum[tid] = 0.f;
        d_chsumsq[tid] = 0.f;
    }
    if (n == 0 && kp < 16) {
        int i = (kp * 256 + tid) * 8;
#pragma unroll
        for (int q = 0; q < 2; ++q) {
            float4 v = *(const float4*)(w_out + i + q * 4);
            *(__half2*)(d_wouth + i + q * 4)     = __floats2half2_rn(v.x, v.y);
            *(__half2*)(d_wouth + i + q * 4 + 2) = __floats2half2_rn(v.z, v.w);
        }
    }
    const float4* r0 = (const float4*)(x + ((size_t)(n * 256 + 2 * kp)) * 4096);
    const float4* r1 = r0 + 1024;
    uint4* dst = (uint4*)d_xh;
    float s0 = 0.f, s1 = 0.f;
#pragma unroll
    for (int it = 0; it < 4; ++it) {
        int f4 = it * 256 + tid;
        float4 a = r0[f4];
        float4 b = r1[f4];
        s0 += a.x + a.y + a.z + a.w;
        s1 += b.x + b.y + b.z + b.w;
        __half2 h0 = __floats2half2_rn(a.x, b.x);
        __half2 h1 = __floats2half2_rn(a.y, b.y);
        __half2 h2 = __floats2half2_rn(a.z, b.z);
        __half2 h3 = __floats2half2_rn(a.w, b.w);
        uint4 w;
        w.x = *(uint32_t*)&h0; w.y = *(uint32_t*)&h1;
        w.z = *(uint32_t*)&h2; w.w = *(uint32_t*)&h3;
        int hwt = f4 >> 5;
        dst[(((size_t)(n * 32 + hwt) * 128 + kp) * 32) + (f4 & 31)] = w;
    }
#pragma unroll
    for (int o = 16; o; o >>= 1) {
        s0 += __shfl_down_sync(0xffffffffu, s0, o);
        s1 += __shfl_down_sync(0xffffffffu, s1, o);
    }
    __shared__ float w0[8], w1[8];
    if ((tid & 31) == 0) { w0[tid >> 5] = s0; w1[tid >> 5] = s1; }
    __syncthreads();
    if (tid < 8) {
        s0 = w0[tid]; s1 = w1[tid];
#pragma unroll
        for (int o = 4; o; o >>= 1) {
            s0 += __shfl_down_sync(0xffu, s0, o);
            s1 += __shfl_down_sync(0xffu, s1, o);
        }
        if (tid == 0) {
            d_xsum[n * 256 + 2 * kp]     = s0;
            d_xsum[n * 256 + 2 * kp + 1] = s1;
        }
    }
}

// ---------------------------------------------------------------------------
// K1: attention prep + fused bias_p (proven)
// ---------------------------------------------------------------------------
__global__ void attn_bias_kernel(const float* __restrict__ w_theta,
                                 const float* __restrict__ b_theta,
                                 const float* __restrict__ w_phi,
                                 const float* __restrict__ b_phi,
                                 const float* __restrict__ b_g,
                                 const float* __restrict__ w_out,
                                 const float* __restrict__ b_out) {
    const int n = blockIdx.x;
    const int i = threadIdx.x;
    __shared__ float xs[DIM];
    __shared__ float ts[DI];
    __shared__ float ps[DI];
    __shared__ float tbs[DI];
    xs[i]       = d_xsum[n * DIM + i];
    xs[i + 128] = d_xsum[n * DIM + 128 + i];
    __syncthreads();

    float dt = 0.f, dp = 0.f;
    const float* wt = w_theta + (size_t)i * DIM;
    const float* wp = w_phi   + (size_t)i * DIM;
#pragma unroll 4
    for (int k = 0; k < DIM; ++k) {
        float xv = xs[k];
        dt = fmaf(wt[k], xv, dt);
        dp = fmaf(wp[k], xv, dp);
    }
    ts[i] = dt * (1.f / 16.f) + 256.f * b_theta[i];
    ps[i] = dp * (1.f / 16.f) + 256.f * b_phi[i];
    __syncthreads();

    const float sc = 0.08838834764831845f;
    float a = ts[i] * sc;
    float m = -1e30f;
#pragma unroll 4
    for (int j = 0; j < DI; ++j) m = fmaxf(m, a * ps[j]);
    float sum = 0.f;
#pragma unroll 4
    for (int j = 0; j < DI; ++j) sum += expf(a * ps[j] - m);
    float inv = 1.f / sum;

    float tbacc = 0.f;
    float* row = d_tp + ((size_t)n * DI + i) * DI;
#pragma unroll 4
    for (int j = 0; j < DI; ++j) {
        float e = expf(a * ps[j] - m) * inv;
        row[j] = e;
        tbacc = fmaf(e, b_g[j], tbacc);
    }
    tbs[i] = tbacc;
    __syncthreads();

#pragma unroll
    for (int cc = 0; cc < 2; ++cc) {
        int c = i + cc * 128;
        float d = 0.f;
        const float* wr = w_out + (size_t)c * DI;
#pragma unroll 4
        for (int j = 0; j < DI; ++j) d = fmaf(wr[j], tbs[j], d);
        d_biasp[n * DIM + c] = (d + b_out[c]) * W2SCALE;
    }
}

// ---------------------------------------------------------------------------
// fragment helpers
// ---------------------------------------------------------------------------
__device__ __forceinline__ void mma16816h(float* c, const uint32_t* a, const uint32_t* b) {
    asm volatile("mma.sync.aligned.m16n8k16.row.col.f32.f16.f16.f32 "
        "{%0,%1,%2,%3}, {%4,%5,%6,%7}, {%8,%9}, {%0,%1,%2,%3};"
        : "+f"(c[0]), "+f"(c[1]), "+f"(c[2]), "+f"(c[3])
        : "r"(a[0]), "r"(a[1]), "r"(a[2]), "r"(a[3]), "r"(b[0]), "r"(b[1]));
}

__device__ __forceinline__ void ldmx4(uint32_t* r, uint32_t addr) {
    asm volatile("ldmatrix.sync.aligned.m8n8.x4.shared.b16 {%0,%1,%2,%3}, [%4];"
        : "=r"(r[0]), "=r"(r[1]), "=r"(r[2]), "=r"(r[3]) : "r"(addr));
}

// ---------------------------------------------------------------------------
// K2: w2combo — phase A: Tsub = tp[n] @ w_g[:, ntile*128..+128) (fp32 SIMT,
// R1-proven tiling), packed k-pair fp16 into smem; phase B: W2h tile =
// (w_out_h @ Tsub) * W2SCALE via the R14-proven mma loop.
// grid (2 mtile, 2 ntile, 32 n), 256 threads.
// ---------------------------------------------------------------------------
#define WC_AK   136
#define WC_SMA  0                          // wout fp16 [128][136]   34816 B
#define WC_SMB  34816                      // Bpk u32   [64][136]    34816 B
#define WC_AS   (WC_SMB + 34816)           // As fp32   [16][128]     8192 B
#define WC_BS   (WC_AS + 8192)             // Bs fp32   [16][128]     8192 B
#define WC_GS   (WC_BS + 8192)             // 86016 B

__global__ void __launch_bounds__(256) w2combo_kernel(const float* __restrict__ w_g) {
    extern __shared__ char smem[];
    const uint32_t sbase = smem_u32(smem);
    const int tid  = threadIdx.x;
    const int lane = tid & 31;
    const int wid  = tid >> 5;
    const int warp_m = wid >> 2;
    const int warp_n = wid & 3;
    const int mtile = blockIdx.x, ntile = blockIdx.y, n = blockIdx.z;

    // load wout A tile early (overlaps phase A latency): 2048 uint4
    {
        const uint4* g = (const uint4*)(d_wouth + (size_t)(mtile * 128) * 128);
#pragma unroll
        for (int it = 0; it < 8; ++it) {
            int idx = it * 256 + tid;
            int r = idx >> 4, c16 = idx & 15;
            *(uint4*)(smem + WC_SMA + r * (WC_AK * 2) + c16 * 16) = g[idx];
        }
    }

    // ---- phase A: fp32 SIMT GEMM Tsub[128 k][128 col] (BM=BN=128, BK=16) ----
    {
        float (*As)[128] = (float(*)[128])(smem + WC_AS);
        float (*Bs)[128] = (float(*)[128])(smem + WC_BS);
        const float* Ag = d_tp + (size_t)n * 16384;         // [128 rows][128 K]
        const float* Bg = w_g + ntile * 128;                // row stride 256

        const int tcol = tid & 15;      // BN/TN = 16
        const int trow = tid >> 4;      // BM/TM = 16

        float acc[8][8];
#pragma unroll
        for (int i = 0; i < 8; ++i)
#pragma unroll
            for (int j = 0; j < 8; ++j) acc[i][j] = 0.f;

        for (int k0 = 0; k0 < 128; k0 += 16) {
#pragma unroll
            for (int it = 0; it < 2; ++it) {
                int idx = (tid + it * 256) * 4;
                int r = idx >> 4, c = idx & 15;             // BK=16
                float4 v = *(const float4*)(Ag + (size_t)r * 128 + k0 + c);
                As[c + 0][r] = v.x; As[c + 1][r] = v.y;
                As[c + 2][r] = v.z; As[c + 3][r] = v.w;
            }
#pragma unroll
            for (int it = 0; it < 2; ++it) {
                int idx = (tid + it * 256) * 4;
                int r = idx >> 7, c = idx & 127;            // BN=128
                *(float4*)(&Bs[r][c]) = *(const float4*)(Bg + (size_t)(k0 + r) * 256 + c);
            }
            __syncthreads();

            float ar[8], br[8];
#pragma unroll
            for (int k = 0; k < 16; ++k) {
#pragma unroll
                for (int i = 0; i < 8; ++i) ar[i] = As[k][trow * 8 + i];
#pragma unroll
                for (int j = 0; j < 8; ++j) br[j] = Bs[k][tcol * 8 + j];
#pragma unroll
                for (int i = 0; i < 8; ++i)
#pragma unroll
                    for (int j = 0; j < 8; ++j) acc[i][j] = fmaf(ar[i], br[j], acc[i][j]);
            }
            __syncthreads();
        }

        // pack to smem B: rows (k of T) pairs -> u32 at [kp][col], pitch 136
#pragma unroll
        for (int ip = 0; ip < 4; ++ip) {
            int kp = trow * 4 + ip;
#pragma unroll
            for (int j = 0; j < 8; ++j) {
                int col = tcol * 8 + j;
                __half2 h = __floats2half2_rn(acc[2 * ip][j], acc[2 * ip + 1][j]);
                *(uint32_t*)(smem + WC_SMB + (kp * 136 + col) * 4) = *(uint32_t*)&h;
            }
        }
    }
    __syncthreads();

    // ---- phase B: mma (R14-proven loop) ----
    float acc[4][4][4];
#pragma unroll
    for (int a = 0; a < 4; ++a)
#pragma unroll
        for (int b = 0; b < 4; ++b)
#pragma unroll
            for (int r = 0; r < 4; ++r) acc[a][b][r] = 0.f;

    const int lrow = (lane & 7) + ((lane >> 3) & 1) * 8;
    const int lkof = (lane >> 4) * 8;

#pragma unroll
    for (int ks = 0; ks < 8; ++ks) {
        const int k0 = ks * 16;
        uint32_t ah[4][4];
#pragma unroll
        for (int mf = 0; mf < 4; ++mf) {
            int r0 = warp_m * 64 + mf * 16 + lrow;
            ldmx4(ah[mf], sbase + WC_SMA + (uint32_t)(r0 * (WC_AK * 2) + (k0 + lkof) * 2));
        }
        uint32_t bb[4][2];
        const int kp0 = ks * 8 + (lane & 3);
#pragma unroll
        for (int nf = 0; nf < 4; ++nf) {
            int col = warp_n * 32 + nf * 8 + (lane >> 2);
            bb[nf][0] = *(const uint32_t*)(smem + WC_SMB + (kp0 * 136 + col) * 4);
            bb[nf][1] = *(const uint32_t*)(smem + WC_SMB + ((kp0 + 4) * 136 + col) * 4);
        }
#pragma unroll
        for (int mf = 0; mf < 4; ++mf)
#pragma unroll
            for (int nf = 0; nf < 4; ++nf)
                mma16816h(acc[mf][nf], ah[mf], bb[nf]);
    }

    const int colbase = warp_n * 32 + (lane & 3) * 2;
    __half* dst = d_W2h + (size_t)n * 65536 + (size_t)(mtile * 128) * 256 + ntile * 128;
#pragma unroll
    for (int mf = 0; mf < 4; ++mf) {
#pragma unroll
        for (int half = 0; half < 2; ++half) {
            int row = warp_m * 64 + mf * 16 + (lane >> 2) + half * 8;
#pragma unroll
            for (int nf = 0; nf < 4; ++nf) {
                __half2 h = __floats2half2_rn(acc[mf][nf][half * 2 + 0] * W2SCALE,
                                              acc[mf][nf][half * 2 + 1] * W2SCALE);
                *(__half2*)(dst + (size_t)row * 256 + nf * 8 + colbase) = h;
            }
        }
    }
}

// ---------------------------------------------------------------------------
// K3: main tensor-core GEMM — unchanged from R11/R14 (passing); ncu target.
// ---------------------------------------------------------------------------
#define AK    264
#define SM_A  0
#define SM_B  (128*AK*2)               // 67584
#define BROW  136
#define CBUF  (16*BROW*4)              // 8704
#define RACC  (SM_B + 4*CBUF)          // 102400
#define GS    (RACC + 1024)            // 103424

__device__ __forceinline__ void issue_chunk(uint32_t dstb, const uint32_t* src, int tid) {
    const int r = tid >> 4;
    const int qo = (tid & 15) * 8;
    uint32_t dsm = dstb + r * 544 + qo * 4;
    const void* g0 = src + r * 128 + qo;
    const void* g1 = src + r * 128 + qo + 4;
    asm volatile("cp.async.cg.shared.global [%0], [%1], 16;" :: "r"(dsm), "l"(g0));
    asm volatile("cp.async.cg.shared.global [%0], [%1], 16;" :: "r"(dsm + 16), "l"(g1));
    asm volatile("cp.async.commit_group;" ::: "memory");
}

__global__ void __launch_bounds__(256, 2) mma_gemm() {
    extern __shared__ char smem[];
    const uint32_t sbase = smem_u32(smem);
    const int tid  = threadIdx.x;
    const int lane = tid & 31;
    const int wid  = tid >> 5;
    const int warp_m = wid >> 2;
    const int warp_n = wid & 3;
    const int bid = blockIdx.x;
    const int m = bid & 1, pair = (bid >> 1) & 15, n = bid >> 5;

    ((float*)(smem + RACC))[tid] = 0.f;

    {
        const uint4* gh = (const uint4*)(d_W2h + ((size_t)n * 256 + m * 128) * 256);
#pragma unroll
        for (int i = 0; i < 16; ++i) {
            int idx = i * 256 + tid;
            int r = idx >> 5, c = idx & 31;
            *(uint4*)(smem + SM_A + r * (AK * 2) + c * 16) = gh[idx];
        }
    }

    float acc[4][4][4];
#pragma unroll
    for (int a = 0; a < 4; ++a)
#pragma unroll
        for (int b = 0; b < 4; ++b)
#pragma unroll
            for (int r = 0; r < 4; ++r) acc[a][b][r] = 0.f;

    const uint32_t* xbase = d_xh + ((size_t)(n * 32 + pair * 2) * 128) * 128;

    issue_chunk(sbase + SM_B + 0 * CBUF, xbase + 0 * 2048, tid);
    issue_chunk(sbase + SM_B + 1 * CBUF, xbase + 1 * 2048, tid);
    issue_chunk(sbase + SM_B + 2 * CBUF, xbase + 2 * 2048, tid);

    const int colbase = warp_n * 32 + (lane & 3) * 2;
    const float* biasg = d_biasp + n * 256 + m * 128;
    float* racc = (float*)(smem + RACC);
    const int lrow = (lane & 7) + ((lane >> 3) & 1) * 8;
    const int lkof = (lane >> 4) * 8;

    for (int cc = 0; cc < 16; ++cc) {
        const uint32_t b_base = SM_B + (cc & 3) * CBUF;

        if (cc < 13) {
            issue_chunk(sbase + SM_B + ((cc + 3) & 3) * CBUF, xbase + (size_t)(cc + 3) * 2048, tid);
            asm volatile("cp.async.wait_group 3;" ::: "memory");
        } else if (cc == 13) {
            asm volatile("cp.async.wait_group 2;" ::: "memory");
        } else if (cc == 14) {
            asm volatile("cp.async.wait_group 1;" ::: "memory");
        } else {
            asm volatile("cp.async.wait_group 0;" ::: "memory");
        }
        __syncthreads();

#pragma unroll
        for (int ks = 0; ks < 2; ++ks) {
            const int k0c = (cc & 7) * 32 + ks * 16;
            uint32_t ah[4][4];
#pragma unroll
            for (int mf = 0; mf < 4; ++mf) {
                int r0 = warp_m * 64 + mf * 16 + lrow;
                uint32_t off = (uint32_t)(r0 * (AK * 2) + (k0c + lkof) * 2);
                ldmx4(ah[mf], sbase + SM_A + off);
            }
            uint32_t bb[4][2];
            const int kp0 = ks * 8 + (lane & 3);
#pragma unroll
            for (int nf = 0; nf < 4; ++nf) {
                int col = warp_n * 32 + nf * 8 + (lane >> 2);
                bb[nf][0] = *(const uint32_t*)(smem + b_base + (kp0 * BROW + col) * 4);
                bb[nf][1] = *(const uint32_t*)(smem + b_base + ((kp0 + 4) * BROW + col) * 4);
            }
#pragma unroll
            for (int mf = 0; mf < 4; ++mf)
#pragma unroll
                for (int nf = 0; nf < 4; ++nf)
                    mma16816h(acc[mf][nf], ah[mf], bb[nf]);
        }
        __syncthreads();

        if ((cc & 7) == 7) {
            const int tile = cc >> 3;
            const int hwt = pair * 2 + tile;
            __half* pg = d_ph + ((size_t)n * 256 + m * 128) * 4096 + hwt * 128;
#pragma unroll
            for (int mf = 0; mf < 4; ++mf) {
#pragma unroll
                for (int half = 0; half < 2; ++half) {
                    int row = warp_m * 64 + mf * 16 + (lane >> 2) + half * 8;
                    float bias = biasg[row];
                    float s = 0.f, s2 = 0.f;
#pragma unroll
                    for (int nf = 0; nf < 4; ++nf) {
                        float v0 = acc[mf][nf][half * 2 + 0] + bias;
                        float v1 = acc[mf][nf][half * 2 + 1] + bias;
                        s += v0 + v1;
                        s2 += v0 * v0 + v1 * v1;
                        *(__half2*)(pg + (size_t)row * 4096 + nf * 8 + colbase) =
                            __floats2half2_rn(v0, v1);
                    }
                    s  += __shfl_xor_sync(0xffffffffu, s, 1);
                    s  += __shfl_xor_sync(0xffffffffu, s, 2);
                    s2 += __shfl_xor_sync(0xffffffffu, s2, 1);
                    s2 += __shfl_xor_sync(0xffffffffu, s2, 2);
                    if ((lane & 3) == 0) {
                        atomicAdd(&racc[row * 2],     s);
                        atomicAdd(&racc[row * 2 + 1], s2);
                    }
                }
            }
#pragma unroll
            for (int a = 0; a < 4; ++a)
#pragma unroll
                for (int b = 0; b < 4; ++b)
#pragma unroll
                    for (int r = 0; r < 4; ++r) acc[a][b][r] = 0.f;
        }
    }

    __syncthreads();
    if (tid < 128) {
        atomicAdd(&d_chsum[m * 128 + tid],   racc[tid * 2]);
        atomicAdd(&d_chsumsq[m * 128 + tid], racc[tid * 2 + 1]);
    }
}

// ---------------------------------------------------------------------------
// K4: out = x + scale*p + shift; scale/shift computed inline from stats.
// ---------------------------------------------------------------------------
__global__ void out2_kernel(float* __restrict__ out,
                            const float* __restrict__ gamma,
                            const float* __restrict__ beta) {
    const size_t g = ((size_t)blockIdx.x * 256 + threadIdx.x) * 4;
    const int hw32 = (int)(g & 127);
    const int kp   = (int)((g >> 7) & 127);
    const int hwt  = (int)((g >> 14) & 31);
    const int n    = (int)(g >> 19);
    const int c0 = 2 * kp, c1 = c0 + 1;

    const float inv_cnt = 1.f / (float)CNT;
    float mean0 = d_chsum[c0] * inv_cnt;
    float var0  = d_chsumsq[c0] * inv_cnt - mean0 * mean0;
    float a0 = gamma[c0] * rsqrtf(var0 + 1e-5f * W2SCALE * W2SCALE);
    float b0 = beta[c0] - a0 * mean0;
    float mean1 = d_chsum[c1] * inv_cnt;
    float var1  = d_chsumsq[c1] * inv_cnt - mean1 * mean1;
    float a1 = gamma[c1] * rsqrtf(var1 + 1e-5f * W2SCALE * W2SCALE);
    float b1 = beta[c1] - a1 * mean1;

    uint4 xw = *(const uint4*)(d_xh + g);
    const size_t hwg = (size_t)hwt * 128 + hw32;
    uint2 p0 = *(const uint2*)(d_ph + ((size_t)(n * 256 + c0)) * 4096 + hwg);
    uint2 p1 = *(const uint2*)(d_ph + ((size_t)(n * 256 + c1)) * 4096 + hwg);

    float2 x0a = __half22float2(*(__half2*)&xw.x);
    float2 x0b = __half22float2(*(__half2*)&xw.y);
    float2 x0c = __half22float2(*(__half2*)&xw.z);
    float2 x0d = __half22float2(*(__half2*)&xw.w);
    float2 p0a = __half22float2(*(__half2*)&p0.x);
    float2 p0b = __half22float2(*(__half2*)&p0.y);
    float2 p1a = __half22float2(*(__half2*)&p1.x);
    float2 p1b = __half22float2(*(__half2*)&p1.y);

    float4 o0, o1;
    o0.x = fmaf(a0, p0a.x, x0a.x + b0);
    o0.y = fmaf(a0, p0a.y, x0b.x + b0);
    o0.z = fmaf(a0, p0b.x, x0c.x + b0);
    o0.w = fmaf(a0, p0b.y, x0d.x + b0);
    o1.x = fmaf(a1, p1a.x, x0a.y + b1);
    o1.y = fmaf(a1, p1a.y, x0b.y + b1);
    o1.z = fmaf(a1, p1b.x, x0c.y + b1);
    o1.w = fmaf(a1, p1b.y, x0d.y + b1);

    *(float4*)(out + ((size_t)(n * 256 + c0)) * 4096 + hwg) = o0;
    *(float4*)(out + ((size_t)(n * 256 + c1)) * 4096 + hwg) = o1;
}

// ---------------------------------------------------------------------------
// launch — mma_gemm at index 3 (the empirically profiled slot)
// ---------------------------------------------------------------------------
extern "C" void kernel_launch(void* const* d_in, const int* in_sizes, int n_in,
                              void* d_out, int out_size) {
    const float* x       = (const float*)d_in[0];
    const float* w_theta = (const float*)d_in[1];
    const float* b_theta = (const float*)d_in[2];
    const float* w_phi   = (const float*)d_in[3];
    const float* b_phi   = (const float*)d_in[4];
    const float* w_g     = (const float*)d_in[5];
    const float* b_g     = (const float*)d_in[6];
    const float* w_out   = (const float*)d_in[7];
    const float* b_out   = (const float*)d_in[8];
    const float* gamma   = (const float*)d_in[9];
    const float* beta    = (const float*)d_in[10];
    float* out = (float*)d_out;
    (void)in_sizes; (void)n_in; (void)out_size;

    cudaFuncSetAttribute(mma_gemm, cudaFuncAttributeMaxDynamicSharedMemorySize, GS);
    cudaFuncSetAttribute(w2combo_kernel, cudaFuncAttributeMaxDynamicSharedMemorySize, WC_GS);

    cvtxsum_kernel<<<dim3(128, 32), 256>>>(x, w_out);                   // 0
    attn_bias_kernel<<<NB, 128>>>(w_theta, b_theta, w_phi, b_phi,       // 1
                                  b_g, w_out, b_out);
    w2combo_kernel<<<dim3(2, 2, NB), 256, WC_GS>>>(w_g);                // 2
    mma_gemm<<<1024, 256, GS>>>();                                      // 3  <- ncu
    out2_kernel<<<16384, 256>>>(out, gamma, beta);                      // 4
}

// round 16
// speedup vs baseline: 1.0226x; 1.0226x over previous
#include <cuda_runtime.h>
#include <cuda_bf16.h>
#include <cuda_fp16.h>
#include <math.h>
#include <stdint.h>

#define NB   32
#define DIM  256
#define DI   128
#define HW   4096
#define CNT  (NB*HW)
#define W2SCALE 256.0f   // scale W2 & bias_p; BN normalization cancels it exactly

// ---------------------------------------------------------------------------
// Device scratch
// ---------------------------------------------------------------------------
__device__ float    d_xsum[NB*DIM];
__device__ float    d_tp[NB*DI*DI];
__device__ float    d_biasp[NB*DIM];
__device__ __half   d_wouth[DIM*DI];                 // w_out fp16 [256][128]
__device__ uint32_t d_Tpk[NB*64*256];                // T fp16 k-pair packed [n][kp64][col256]
__device__ __half   d_W2h[(size_t)NB*DIM*DIM];
// x in fp16, k-pair packed: [n][hwt(32)][kp(128)][hw(128)] u32
__device__ uint32_t d_xh[(size_t)NB*32*128*128];     // 67 MB
__device__ __half   d_ph[(size_t)NB*DIM*HW];         // pre-BN p (scaled x256), 67 MB
__device__ float    d_chsum[DIM];
__device__ float    d_chsumsq[DIM];

__device__ __forceinline__ uint32_t smem_u32(const void* p) {
    uint32_t a;
    asm("{ .reg .u64 t; cvta.to.shared.u64 t, %1; cvt.u32.u64 %0, t; }" : "=r"(a) : "l"(p));
    return a;
}

// ---------------------------------------------------------------------------
// K0: convert x -> packed fp16 blob + per-(n,c) channel sums.
// Blocks (kp<16, n==0) also convert w_out fp32->fp16. Block (0,0) zeroes stats.
// ---------------------------------------------------------------------------
__global__ void cvtxsum_kernel(const float* __restrict__ x,
                               const float* __restrict__ w_out) {
    const int kp = blockIdx.x, n = blockIdx.y, tid = threadIdx.x;
    if (n == 0 && kp == 0) {
        d_chsum[tid] = 0.f;
        d_chsumsq[tid] = 0.f;
    }
    if (n == 0 && kp < 16) {
        int i = (kp * 256 + tid) * 8;
#pragma unroll
        for (int q = 0; q < 2; ++q) {
            float4 v = *(const float4*)(w_out + i + q * 4);
            *(__half2*)(d_wouth + i + q * 4)     = __floats2half2_rn(v.x, v.y);
            *(__half2*)(d_wouth + i + q * 4 + 2) = __floats2half2_rn(v.z, v.w);
        }
    }
    const float4* r0 = (const float4*)(x + ((size_t)(n * 256 + 2 * kp)) * 4096);
    const float4* r1 = r0 + 1024;
    uint4* dst = (uint4*)d_xh;
    float s0 = 0.f, s1 = 0.f;
#pragma unroll
    for (int it = 0; it < 4; ++it) {
        int f4 = it * 256 + tid;
        float4 a = r0[f4];
        float4 b = r1[f4];
        s0 += a.x + a.y + a.z + a.w;
        s1 += b.x + b.y + b.z + b.w;
        __half2 h0 = __floats2half2_rn(a.x, b.x);
        __half2 h1 = __floats2half2_rn(a.y, b.y);
        __half2 h2 = __floats2half2_rn(a.z, b.z);
        __half2 h3 = __floats2half2_rn(a.w, b.w);
        uint4 w;
        w.x = *(uint32_t*)&h0; w.y = *(uint32_t*)&h1;
        w.z = *(uint32_t*)&h2; w.w = *(uint32_t*)&h3;
        int hwt = f4 >> 5;
        dst[(((size_t)(n * 32 + hwt) * 128 + kp) * 32) + (f4 & 31)] = w;
    }
#pragma unroll
    for (int o = 16; o; o >>= 1) {
        s0 += __shfl_down_sync(0xffffffffu, s0, o);
        s1 += __shfl_down_sync(0xffffffffu, s1, o);
    }
    __shared__ float w0[8], w1[8];
    if ((tid & 31) == 0) { w0[tid >> 5] = s0; w1[tid >> 5] = s1; }
    __syncthreads();
    if (tid < 8) {
        s0 = w0[tid]; s1 = w1[tid];
#pragma unroll
        for (int o = 4; o; o >>= 1) {
            s0 += __shfl_down_sync(0xffu, s0, o);
            s1 += __shfl_down_sync(0xffu, s1, o);
        }
        if (tid == 0) {
            d_xsum[n * 256 + 2 * kp]     = s0;
            d_xsum[n * 256 + 2 * kp + 1] = s1;
        }
    }
}

// ---------------------------------------------------------------------------
// K1: attention prep + fused bias_p (proven)
// ---------------------------------------------------------------------------
__global__ void attn_bias_kernel(const float* __restrict__ w_theta,
                                 const float* __restrict__ b_theta,
                                 const float* __restrict__ w_phi,
                                 const float* __restrict__ b_phi,
                                 const float* __restrict__ b_g,
                                 const float* __restrict__ w_out,
                                 const float* __restrict__ b_out) {
    const int n = blockIdx.x;
    const int i = threadIdx.x;
    __shared__ float xs[DIM];
    __shared__ float ts[DI];
    __shared__ float ps[DI];
    __shared__ float tbs[DI];
    xs[i]       = d_xsum[n * DIM + i];
    xs[i + 128] = d_xsum[n * DIM + 128 + i];
    __syncthreads();

    float dt = 0.f, dp = 0.f;
    const float* wt = w_theta + (size_t)i * DIM;
    const float* wp = w_phi   + (size_t)i * DIM;
#pragma unroll 4
    for (int k = 0; k < DIM; ++k) {
        float xv = xs[k];
        dt = fmaf(wt[k], xv, dt);
        dp = fmaf(wp[k], xv, dp);
    }
    ts[i] = dt * (1.f / 16.f) + 256.f * b_theta[i];
    ps[i] = dp * (1.f / 16.f) + 256.f * b_phi[i];
    __syncthreads();

    const float sc = 0.08838834764831845f;
    float a = ts[i] * sc;
    float m = -1e30f;
#pragma unroll 4
    for (int j = 0; j < DI; ++j) m = fmaxf(m, a * ps[j]);
    float sum = 0.f;
#pragma unroll 4
    for (int j = 0; j < DI; ++j) sum += expf(a * ps[j] - m);
    float inv = 1.f / sum;

    float tbacc = 0.f;
    float* row = d_tp + ((size_t)n * DI + i) * DI;
#pragma unroll 4
    for (int j = 0; j < DI; ++j) {
        float e = expf(a * ps[j] - m) * inv;
        row[j] = e;
        tbacc = fmaf(e, b_g[j], tbacc);
    }
    tbs[i] = tbacc;
    __syncthreads();

#pragma unroll
    for (int cc = 0; cc < 2; ++cc) {
        int c = i + cc * 128;
        float d = 0.f;
        const float* wr = w_out + (size_t)c * DI;
#pragma unroll 4
        for (int j = 0; j < DI; ++j) d = fmaf(wr[j], tbs[j], d);
        d_biasp[n * DIM + c] = (d + b_out[c]) * W2SCALE;
    }
}

// ---------------------------------------------------------------------------
// K2: T = tp @ w_g (fp32 compute), output as k-pair-packed fp16 (R14-proven)
// ---------------------------------------------------------------------------
__global__ void sgemm_Tpk(const float* __restrict__ w_g) {
    constexpr int BM = 64, BN = 64, BK = 32, TM = 4, TN = 4;
    constexpr int THREADS = (BM / TM) * (BN / TN);   // 256
    const int b = blockIdx.z;
    const float* A = d_tp + (long long)b * DI * DI;
    const float* B = w_g;
    const int N = 256, K = 128;

    __shared__ float As[BK][BM];
    __shared__ float Bs[BK][BN];

    const int tid  = threadIdx.x;
    const int tcol = tid % (BN / TN);
    const int trow = tid / (BN / TN);

    const float* Ag = A + (long long)blockIdx.y * BM * K;
    const float* Bg = B + blockIdx.x * BN;

    float acc[TM][TN];
#pragma unroll
    for (int i = 0; i < TM; ++i)
#pragma unroll
        for (int j = 0; j < TN; ++j) acc[i][j] = 0.f;

    for (int k0 = 0; k0 < K; k0 += BK) {
#pragma unroll
        for (int it = 0; it < (BM * BK) / (THREADS * 4); ++it) {
            int idx = (tid + it * THREADS) * 4;
            int r = idx / BK, c = idx % BK;
            float4 v = *(const float4*)(Ag + (long long)r * K + k0 + c);
            As[c + 0][r] = v.x; As[c + 1][r] = v.y;
            As[c + 2][r] = v.z; As[c + 3][r] = v.w;
        }
#pragma unroll
        for (int it = 0; it < (BK * BN) / (THREADS * 4); ++it) {
            int idx = (tid + it * THREADS) * 4;
            int r = idx / BN, c = idx % BN;
            *(float4*)(&Bs[r][c]) = *(const float4*)(Bg + (long long)(k0 + r) * N + c);
        }
        __syncthreads();

        float ar[TM], br[TN];
#pragma unroll
        for (int k = 0; k < BK; ++k) {
#pragma unroll
            for (int i = 0; i < TM; ++i) ar[i] = As[k][trow * TM + i];
#pragma unroll
            for (int j = 0; j < TN; ++j) br[j] = Bs[k][tcol * TN + j];
#pragma unroll
            for (int i = 0; i < TM; ++i)
#pragma unroll
                for (int j = 0; j < TN; ++j) acc[i][j] = fmaf(ar[i], br[j], acc[i][j]);
        }
        __syncthreads();
    }

    const int col0 = blockIdx.x * BN + tcol * TN;
#pragma unroll
    for (int ip = 0; ip < 2; ++ip) {
        int r0 = blockIdx.y * BM + trow * TM + 2 * ip;
        int kp = r0 >> 1;
        uint32_t w[4];
#pragma unroll
        for (int j = 0; j < TN; ++j) {
            __half2 h = __floats2half2_rn(acc[2 * ip][j], acc[2 * ip + 1][j]);
            w[j] = *(uint32_t*)&h;
        }
        *(uint4*)(d_Tpk + ((size_t)b * 64 + kp) * 256 + col0) = make_uint4(w[0], w[1], w[2], w[3]);
    }
}

// ---------------------------------------------------------------------------
// fragment helpers
// ---------------------------------------------------------------------------
__device__ __forceinline__ void mma16816h(float* c, const uint32_t* a, const uint32_t* b) {
    asm volatile("mma.sync.aligned.m16n8k16.row.col.f32.f16.f16.f32 "
        "{%0,%1,%2,%3}, {%4,%5,%6,%7}, {%8,%9}, {%0,%1,%2,%3};"
        : "+f"(c[0]), "+f"(c[1]), "+f"(c[2]), "+f"(c[3])
        : "r"(a[0]), "r"(a[1]), "r"(a[2]), "r"(a[3]), "r"(b[0]), "r"(b[1]));
}

__device__ __forceinline__ void ldmx4(uint32_t* r, uint32_t addr) {
    asm volatile("ldmatrix.sync.aligned.m8n8.x4.shared.b16 {%0,%1,%2,%3}, [%4];"
        : "=r"(r[0]), "=r"(r[1]), "=r"(r[2]), "=r"(r[3]) : "r"(addr));
}

// ---------------------------------------------------------------------------
// K3: w2mma — W2h = (w_out_h @ T) * W2SCALE (R14-proven)
// ---------------------------------------------------------------------------
#define W2_AK   136
#define W2_SMA  0
#define W2_SMB  (128*W2_AK*2)           // 34816
#define W2_GS   (W2_SMB + 64*136*4)     // 69632

__global__ void __launch_bounds__(256) w2mma_kernel() {
    extern __shared__ char smem[];
    const uint32_t sbase = smem_u32(smem);
    const int tid  = threadIdx.x;
    const int lane = tid & 31;
    const int wid  = tid >> 5;
    const int warp_m = wid >> 2;
    const int warp_n = wid & 3;
    const int mtile = blockIdx.x, ntile = blockIdx.y, n = blockIdx.z;

    {
        const uint4* g = (const uint4*)(d_wouth + (size_t)(mtile * 128) * 128);
#pragma unroll
        for (int it = 0; it < 8; ++it) {
            int idx = it * 256 + tid;
            int r = idx >> 4, c16 = idx & 15;
            *(uint4*)(smem + W2_SMA + r * (W2_AK * 2) + c16 * 16) = g[idx];
        }
    }
    {
        const uint32_t* g = d_Tpk + (size_t)n * 16384 + ntile * 128;
#pragma unroll
        for (int it = 0; it < 8; ++it) {
            int idx = it * 256 + tid;
            int r = idx >> 5, c4 = idx & 31;
            *(uint4*)(smem + W2_SMB + (r * 136 + c4 * 4) * 4) =
                *(const uint4*)(g + r * 256 + c4 * 4);
        }
    }
    __syncthreads();

    float acc[4][4][4];
#pragma unroll
    for (int a = 0; a < 4; ++a)
#pragma unroll
        for (int b = 0; b < 4; ++b)
#pragma unroll
            for (int r = 0; r < 4; ++r) acc[a][b][r] = 0.f;

    const int lrow = (lane & 7) + ((lane >> 3) & 1) * 8;
    const int lkof = (lane >> 4) * 8;

#pragma unroll
    for (int ks = 0; ks < 8; ++ks) {
        const int k0 = ks * 16;
        uint32_t ah[4][4];
#pragma unroll
        for (int mf = 0; mf < 4; ++mf) {
            int r0 = warp_m * 64 + mf * 16 + lrow;
            ldmx4(ah[mf], sbase + W2_SMA + (uint32_t)(r0 * (W2_AK * 2) + (k0 + lkof) * 2));
        }
        uint32_t bb[4][2];
        const int kp0 = ks * 8 + (lane & 3);
#pragma unroll
        for (int nf = 0; nf < 4; ++nf) {
            int col = warp_n * 32 + nf * 8 + (lane >> 2);
            bb[nf][0] = *(const uint32_t*)(smem + W2_SMB + (kp0 * 136 + col) * 4);
            bb[nf][1] = *(const uint32_t*)(smem + W2_SMB + ((kp0 + 4) * 136 + col) * 4);
        }
#pragma unroll
        for (int mf = 0; mf < 4; ++mf)
#pragma unroll
            for (int nf = 0; nf < 4; ++nf)
                mma16816h(acc[mf][nf], ah[mf], bb[nf]);
    }

    const int colbase = warp_n * 32 + (lane & 3) * 2;
    __half* dst = d_W2h + (size_t)n * 65536 + (size_t)(mtile * 128) * 256 + ntile * 128;
#pragma unroll
    for (int mf = 0; mf < 4; ++mf) {
#pragma unroll
        for (int half = 0; half < 2; ++half) {
            int row = warp_m * 64 + mf * 16 + (lane >> 2) + half * 8;
#pragma unroll
            for (int nf = 0; nf < 4; ++nf) {
                __half2 h = __floats2half2_rn(acc[mf][nf][half * 2 + 0] * W2SCALE,
                                              acc[mf][nf][half * 2 + 1] * W2SCALE);
                *(__half2*)(dst + (size_t)row * 256 + nf * 8 + colbase) = h;
            }
        }
    }
}

// ---------------------------------------------------------------------------
// K4: main tensor-core GEMM — SINGLE sync per chunk (wait -> sync -> issue ->
// compute). Wait depth 2 (issues trail the wait). 16 barriers instead of 32.
// ---------------------------------------------------------------------------
#define AK    264
#define SM_A  0
#define SM_B  (128*AK*2)               // 67584
#define BROW  136
#define CBUF  (16*BROW*4)              // 8704
#define RACC  (SM_B + 4*CBUF)          // 102400
#define GS    (RACC + 1024)            // 103424

__device__ __forceinline__ void issue_chunk(uint32_t dstb, const uint32_t* src, int tid) {
    const int r = tid >> 4;
    const int qo = (tid & 15) * 8;
    uint32_t dsm = dstb + r * 544 + qo * 4;
    const void* g0 = src + r * 128 + qo;
    const void* g1 = src + r * 128 + qo + 4;
    asm volatile("cp.async.cg.shared.global [%0], [%1], 16;" :: "r"(dsm), "l"(g0));
    asm volatile("cp.async.cg.shared.global [%0], [%1], 16;" :: "r"(dsm + 16), "l"(g1));
    asm volatile("cp.async.commit_group;" ::: "memory");
}

__global__ void __launch_bounds__(256, 2) mma_gemm() {
    extern __shared__ char smem[];
    const uint32_t sbase = smem_u32(smem);
    const int tid  = threadIdx.x;
    const int lane = tid & 31;
    const int wid  = tid >> 5;
    const int warp_m = wid >> 2;
    const int warp_n = wid & 3;
    const int bid = blockIdx.x;
    const int m = bid & 1, pair = (bid >> 1) & 15, n = bid >> 5;

    ((float*)(smem + RACC))[tid] = 0.f;

    {
        const uint4* gh = (const uint4*)(d_W2h + ((size_t)n * 256 + m * 128) * 256);
#pragma unroll
        for (int i = 0; i < 16; ++i) {
            int idx = i * 256 + tid;
            int r = idx >> 5, c = idx & 31;
            *(uint4*)(smem + SM_A + r * (AK * 2) + c * 16) = gh[idx];
        }
    }

    float acc[4][4][4];
#pragma unroll
    for (int a = 0; a < 4; ++a)
#pragma unroll
        for (int b = 0; b < 4; ++b)
#pragma unroll
            for (int r = 0; r < 4; ++r) acc[a][b][r] = 0.f;

    const uint32_t* xbase = d_xh + ((size_t)(n * 32 + pair * 2) * 128) * 128;

    issue_chunk(sbase + SM_B + 0 * CBUF, xbase + 0 * 2048, tid);
    issue_chunk(sbase + SM_B + 1 * CBUF, xbase + 1 * 2048, tid);
    issue_chunk(sbase + SM_B + 2 * CBUF, xbase + 2 * 2048, tid);

    const int colbase = warp_n * 32 + (lane & 3) * 2;
    const float* biasg = d_biasp + n * 256 + m * 128;
    float* racc = (float*)(smem + RACC);
    const int lrow = (lane & 7) + ((lane >> 3) & 1) * 8;
    const int lkof = (lane >> 4) * 8;

    for (int cc = 0; cc < 16; ++cc) {
        const uint32_t b_base = SM_B + (cc & 3) * CBUF;

        // wait for chunk cc (issues trail: pending <= 2 means cc arrived)
        if (cc <= 13) {
            asm volatile("cp.async.wait_group 2;" ::: "memory");
        } else if (cc == 14) {
            asm volatile("cp.async.wait_group 1;" ::: "memory");
        } else {
            asm volatile("cp.async.wait_group 0;" ::: "memory");
        }
        __syncthreads();   // chunk cc visible; all warps done reading buf (cc-1)&3

        // refill buffer (cc-1)&3 with chunk cc+3 (safe: after the sync)
        if (cc < 13)
            issue_chunk(sbase + SM_B + ((cc + 3) & 3) * CBUF,
                        xbase + (size_t)(cc + 3) * 2048, tid);

        // ---- compute: 2 k16 steps over this 16-kp chunk ----
#pragma unroll
        for (int ks = 0; ks < 2; ++ks) {
            const int k0c = (cc & 7) * 32 + ks * 16;
            uint32_t ah[4][4];
#pragma unroll
            for (int mf = 0; mf < 4; ++mf) {
                int r0 = warp_m * 64 + mf * 16 + lrow;
                uint32_t off = (uint32_t)(r0 * (AK * 2) + (k0c + lkof) * 2);
                ldmx4(ah[mf], sbase + SM_A + off);
            }
            uint32_t bb[4][2];
            const int kp0 = ks * 8 + (lane & 3);
#pragma unroll
            for (int nf = 0; nf < 4; ++nf) {
                int col = warp_n * 32 + nf * 8 + (lane >> 2);
                bb[nf][0] = *(const uint32_t*)(smem + b_base + (kp0 * BROW + col) * 4);
                bb[nf][1] = *(const uint32_t*)(smem + b_base + ((kp0 + 4) * BROW + col) * 4);
            }
#pragma unroll
            for (int mf = 0; mf < 4; ++mf)
#pragma unroll
                for (int nf = 0; nf < 4; ++nf)
                    mma16816h(acc[mf][nf], ah[mf], bb[nf]);
        }

        // ---- per-tile epilogue after chunks 7 and 15 ----
        if ((cc & 7) == 7) {
            const int tile = cc >> 3;
            const int hwt = pair * 2 + tile;
            __half* pg = d_ph + ((size_t)n * 256 + m * 128) * 4096 + hwt * 128;
#pragma unroll
            for (int mf = 0; mf < 4; ++mf) {
#pragma unroll
                for (int half = 0; half < 2; ++half) {
                    int row = warp_m * 64 + mf * 16 + (lane >> 2) + half * 8;
                    float bias = biasg[row];
                    float s = 0.f, s2 = 0.f;
#pragma unroll
                    for (int nf = 0; nf < 4; ++nf) {
                        float v0 = acc[mf][nf][half * 2 + 0] + bias;
                        float v1 = acc[mf][nf][half * 2 + 1] + bias;
                        s += v0 + v1;
                        s2 += v0 * v0 + v1 * v1;
                        *(__half2*)(pg + (size_t)row * 4096 + nf * 8 + colbase) =
                            __floats2half2_rn(v0, v1);
                    }
                    s  += __shfl_xor_sync(0xffffffffu, s, 1);
                    s  += __shfl_xor_sync(0xffffffffu, s, 2);
                    s2 += __shfl_xor_sync(0xffffffffu, s2, 1);
                    s2 += __shfl_xor_sync(0xffffffffu, s2, 2);
                    if ((lane & 3) == 0) {
                        atomicAdd(&racc[row * 2],     s);
                        atomicAdd(&racc[row * 2 + 1], s2);
                    }
                }
            }
#pragma unroll
            for (int a = 0; a < 4; ++a)
#pragma unroll
                for (int b = 0; b < 4; ++b)
#pragma unroll
                    for (int r = 0; r < 4; ++r) acc[a][b][r] = 0.f;
        }
    }

    __syncthreads();
    if (tid < 128) {
        atomicAdd(&d_chsum[m * 128 + tid],   racc[tid * 2]);
        atomicAdd(&d_chsumsq[m * 128 + tid], racc[tid * 2 + 1]);
    }
}

// ---------------------------------------------------------------------------
// K5: out = x + scale*p + shift; scale/shift computed inline from stats.
// ---------------------------------------------------------------------------
__global__ void out2_kernel(float* __restrict__ out,
                            const float* __restrict__ gamma,
                            const float* __restrict__ beta) {
    const size_t g = ((size_t)blockIdx.x * 256 + threadIdx.x) * 4;
    const int hw32 = (int)(g & 127);
    const int kp   = (int)((g >> 7) & 127);
    const int hwt  = (int)((g >> 14) & 31);
    const int n    = (int)(g >> 19);
    const int c0 = 2 * kp, c1 = c0 + 1;

    const float inv_cnt = 1.f / (float)CNT;
    float mean0 = d_chsum[c0] * inv_cnt;
    float var0  = d_chsumsq[c0] * inv_cnt - mean0 * mean0;
    float a0 = gamma[c0] * rsqrtf(var0 + 1e-5f * W2SCALE * W2SCALE);
    float b0 = beta[c0] - a0 * mean0;
    float mean1 = d_chsum[c1] * inv_cnt;
    float var1  = d_chsumsq[c1] * inv_cnt - mean1 * mean1;
    float a1 = gamma[c1] * rsqrtf(var1 + 1e-5f * W2SCALE * W2SCALE);
    float b1 = beta[c1] - a1 * mean1;

    uint4 xw = *(const uint4*)(d_xh + g);
    const size_t hwg = (size_t)hwt * 128 + hw32;
    uint2 p0 = *(const uint2*)(d_ph + ((size_t)(n * 256 + c0)) * 4096 + hwg);
    uint2 p1 = *(const uint2*)(d_ph + ((size_t)(n * 256 + c1)) * 4096 + hwg);

    float2 x0a = __half22float2(*(__half2*)&xw.x);
    float2 x0b = __half22float2(*(__half2*)&xw.y);
    float2 x0c = __half22float2(*(__half2*)&xw.z);
    float2 x0d = __half22float2(*(__half2*)&xw.w);
    float2 p0a = __half22float2(*(__half2*)&p0.x);
    float2 p0b = __half22float2(*(__half2*)&p0.y);
    float2 p1a = __half22float2(*(__half2*)&p1.x);
    float2 p1b = __half22float2(*(__half2*)&p1.y);

    float4 o0, o1;
    o0.x = fmaf(a0, p0a.x, x0a.x + b0);
    o0.y = fmaf(a0, p0a.y, x0b.x + b0);
    o0.z = fmaf(a0, p0b.x, x0c.x + b0);
    o0.w = fmaf(a0, p0b.y, x0d.x + b0);
    o1.x = fmaf(a1, p1a.x, x0a.y + b1);
    o1.y = fmaf(a1, p1a.y, x0b.y + b1);
    o1.z = fmaf(a1, p1b.x, x0c.y + b1);
    o1.w = fmaf(a1, p1b.y, x0d.y + b1);

    *(float4*)(out + ((size_t)(n * 256 + c0)) * 4096 + hwg) = o0;
    *(float4*)(out + ((size_t)(n * 256 + c1)) * 4096 + hwg) = o1;
}

// ---------------------------------------------------------------------------
// launch
// ---------------------------------------------------------------------------
extern "C" void kernel_launch(void* const* d_in, const int* in_sizes, int n_in,
                              void* d_out, int out_size) {
    const float* x       = (const float*)d_in[0];
    const float* w_theta = (const float*)d_in[1];
    const float* b_theta = (const float*)d_in[2];
    const float* w_phi   = (const float*)d_in[3];
    const float* b_phi   = (const float*)d_in[4];
    const float* w_g     = (const float*)d_in[5];
    const float* b_g     = (const float*)d_in[6];
    const float* w_out   = (const float*)d_in[7];
    const float* b_out   = (const float*)d_in[8];
    const float* gamma   = (const float*)d_in[9];
    const float* beta    = (const float*)d_in[10];
    float* out = (float*)d_out;
    (void)in_sizes; (void)n_in; (void)out_size;

    cudaFuncSetAttribute(mma_gemm, cudaFuncAttributeMaxDynamicSharedMemorySize, GS);
    cudaFuncSetAttribute(w2mma_kernel, cudaFuncAttributeMaxDynamicSharedMemorySize, W2_GS);

    cvtxsum_kernel<<<dim3(128, 32), 256>>>(x, w_out);                   // 0
    attn_bias_kernel<<<NB, 128>>>(w_theta, b_theta, w_phi, b_phi,       // 1
                                  b_g, w_out, b_out);
    sgemm_Tpk<<<dim3(4, 2, NB), 256>>>(w_g);                            // 2
    w2mma_kernel<<<dim3(2, 2, NB), 256, W2_GS>>>();                     // 3
    mma_gemm<<<1024, 256, GS>>>();                                      // 4
    out2_kernel<<<16384, 256>>>(out, gamma, beta);                      // 5
}